// round 7
// baseline (speedup 1.0000x reference)
#include <cuda_runtime.h>
#include <math.h>

#define NN 100000
#define EE 1250000
#define H  64

// ---------------- scratch (static __device__ — no allocation allowed) ----------------
__device__ __align__(16) float g_bufA[NN * H];
__device__ __align__(16) float g_bufB[NN * H];
__device__ float g_dinv [NN];
__device__ float g_as   [NN];
__device__ float g_ad   [NN];
__device__ int   g_degi [NN];
__device__ int   g_scan [NN];
__device__ int   g_bsum [128];
__device__ int   g_boff [128];
__device__ int   g_row  [NN + 1];
__device__ int   g_cur  [NN];
__device__ int   g_csrc [EE];
__device__ int   g_asmax;
__device__ __align__(16) float g_embed[H];

__device__ __forceinline__ float leaky(float v) { return v > 0.f ? v : 0.2f * v; }
__device__ __forceinline__ int enc_f(float f) {
    int i = __float_as_int(f);
    return i >= 0 ? i : (i ^ 0x7FFFFFFF);
}
__device__ __forceinline__ float dec_f(int i) {
    return __int_as_float(i >= 0 ? i : (i ^ 0x7FFFFFFF));
}

// ---------------- prep: zero degree histogram + embed + asmax ----------------
__global__ void k_prep(int n) {
    int t = blockIdx.x * blockDim.x + threadIdx.x;
    if (t < n) g_degi[t] = 0;
    if (t < 16) ((float4*)g_embed)[t] = make_float4(0.f, 0.f, 0.f, 0.f);
    if (t == 0) g_asmax = (int)0x80000000;   // INT_MIN
}

__global__ void k_deg(const int* __restrict__ dst, int e) {
    int t = blockIdx.x * blockDim.x + threadIdx.x;
    if (t < e) atomicAdd(&g_degi[dst[t]], 1);
}

// ---------------- scans (warp-shuffle based) ----------------
__global__ void k_scan1(int n) {
    __shared__ int wsum[32];
    int i = blockIdx.x * 1024 + threadIdx.x;
    int lane = threadIdx.x & 31, wid = threadIdx.x >> 5;
    int v = (i < n) ? g_degi[i] : 0;
    int s = v;
#pragma unroll
    for (int o = 1; o < 32; o <<= 1) {
        int u = __shfl_up_sync(0xffffffffu, s, o);
        if (lane >= o) s += u;
    }
    if (lane == 31) wsum[wid] = s;
    __syncthreads();
    if (wid == 0) {
        int w = wsum[lane];
#pragma unroll
        for (int o = 1; o < 32; o <<= 1) {
            int u = __shfl_up_sync(0xffffffffu, w, o);
            if (lane >= o) w += u;
        }
        wsum[lane] = w;
    }
    __syncthreads();
    int off = wid ? wsum[wid - 1] : 0;
    s += off;
    if (i < n) g_scan[i] = s;                    // inclusive
    if (threadIdx.x == 1023) g_bsum[blockIdx.x] = s;  // block total
}

__global__ void k_scan2(int nb) {
    __shared__ int wsum[4];
    int t = threadIdx.x, lane = t & 31, wid = t >> 5;
    int v = (t < nb) ? g_bsum[t] : 0;
    int s = v;
#pragma unroll
    for (int o = 1; o < 32; o <<= 1) {
        int u = __shfl_up_sync(0xffffffffu, s, o);
        if (lane >= o) s += u;
    }
    if (lane == 31) wsum[wid] = s;
    __syncthreads();
    int off = 0;
    if (wid > 0) off += wsum[0];
    if (wid > 1) off += wsum[1];
    if (wid > 2) off += wsum[2];
    if (t < nb) g_boff[t] = s + off - v;  // exclusive across blocks
}

__global__ void k_scan3(int n, int e) {
    int i = blockIdx.x * blockDim.x + threadIdx.x;
    if (i < n) {
        int d = g_degi[i];
        int start = g_scan[i] - d + g_boff[i >> 10];
        g_row[i] = start;
        g_cur[i] = start;
        g_dinv[i] = rsqrtf((float)(d + 1));   // +1 self-loop
    }
    if (i == 0) g_row[n] = e;
}

__global__ void k_csr(const int* __restrict__ src, const int* __restrict__ dst, int e) {
    int t = blockIdx.x * blockDim.x + threadIdx.x;
    if (t >= e) return;
    int pos = atomicAdd(&g_cur[dst[t]], 1);
    g_csrc[pos] = src[t];
}

// ---------------- GCN1 fused: gather in F=32 space into smem, then GEMM + bias + relu ----
// 128 nodes/block, 256 threads. xsT[K][128+pad] transposed tile, conflict-free.
__global__ void __launch_bounds__(256) k_gcn1(
    const float* __restrict__ x, const float* __restrict__ W,
    const float* __restrict__ bias, float* __restrict__ out, int n)
{
    constexpr int K = 32, PADN = 129;
    __shared__ float Ws[K * H];        // 8KB
    __shared__ float xsT[K * PADN];    // 16.5KB
    __shared__ float bs[H];
    const int tid  = threadIdx.x;
    const int base = blockIdx.x * 128;

    for (int i = tid; i < K * H; i += 256) Ws[i] = W[i];
    if (tid < H) bs[tid] = bias[tid];

    int rows = n - base; if (rows > 128) rows = 128;

    // gather stage: 4 passes of 32 nodes, 8 lanes/node
    const int c = tid & 7;
    for (int pass = 0; pass < 4; pass++) {
        int r = pass * 32 + (tid >> 3);
        int node = base + r;
        if (r < rows) {
            int beg = g_row[node], end = g_row[node + 1];
            float dd = g_dinv[node];
            float4 self = __ldg((const float4*)x + (size_t)node * 8 + c);
            float4 acc = make_float4(self.x * dd, self.y * dd, self.z * dd, self.w * dd);
            int i = beg;
            for (; i + 2 <= end; i += 2) {
                int s0 = __ldg(&g_csrc[i]);
                int s1 = __ldg(&g_csrc[i + 1]);
                float d0 = __ldg(&g_dinv[s0]);
                float d1 = __ldg(&g_dinv[s1]);
                float4 v0 = __ldg((const float4*)x + (size_t)s0 * 8 + c);
                float4 v1 = __ldg((const float4*)x + (size_t)s1 * 8 + c);
                acc.x += d0 * v0.x + d1 * v1.x;
                acc.y += d0 * v0.y + d1 * v1.y;
                acc.z += d0 * v0.z + d1 * v1.z;
                acc.w += d0 * v0.w + d1 * v1.w;
            }
            if (i < end) {
                int s0 = __ldg(&g_csrc[i]);
                float d0 = __ldg(&g_dinv[s0]);
                float4 v0 = __ldg((const float4*)x + (size_t)s0 * 8 + c);
                acc.x += d0 * v0.x; acc.y += d0 * v0.y;
                acc.z += d0 * v0.z; acc.w += d0 * v0.w;
            }
            int chb = c * 4;
            xsT[(chb + 0) * PADN + r] = acc.x;
            xsT[(chb + 1) * PADN + r] = acc.y;
            xsT[(chb + 2) * PADN + r] = acc.z;
            xsT[(chb + 3) * PADN + r] = acc.w;
        }
    }
    __syncthreads();

    // GEMM stage: 2 threads/node, interleaved float4 channels
    const int r     = tid >> 1;
    const bool valid = (r < rows);
    const int rc    = valid ? r : 0;
    const int half  = tid & 1;

    float acc[32];
#pragma unroll
    for (int j = 0; j < 32; j++) acc[j] = 0.f;

#pragma unroll 4
    for (int k = 0; k < K; k++) {
        float xv = xsT[k * PADN + rc];
        const float4* w4 = (const float4*)&Ws[k * H];
#pragma unroll
        for (int j = 0; j < 8; j++) {
            float4 w = w4[j * 2 + half];
            acc[4*j+0] = fmaf(xv, w.x, acc[4*j+0]);
            acc[4*j+1] = fmaf(xv, w.y, acc[4*j+1]);
            acc[4*j+2] = fmaf(xv, w.z, acc[4*j+2]);
            acc[4*j+3] = fmaf(xv, w.w, acc[4*j+3]);
        }
    }
    if (!valid) return;
    const int node = base + r;
    float d = g_dinv[node];
    float4* o4 = (float4*)&out[(size_t)node * H];
#pragma unroll
    for (int j = 0; j < 8; j++) {
        int ch = (j * 2 + half) * 4;
        o4[j * 2 + half] = make_float4(
            fmaxf(fmaf(acc[4*j+0], d, bs[ch+0]), 0.f),
            fmaxf(fmaf(acc[4*j+1], d, bs[ch+1]), 0.f),
            fmaxf(fmaf(acc[4*j+2], d, bs[ch+2]), 0.f),
            fmaxf(fmaf(acc[4*j+3], d, bs[ch+3]), 0.f));
    }
}

// ---------------- GAT GEMM: h2 = h1 @ W2 ; alpha dots ; global as-max ----------------
__global__ void __launch_bounds__(256) k_gat_gemm(
    const float* __restrict__ in, const float* __restrict__ W,
    float* __restrict__ out,
    const float* __restrict__ avs, const float* __restrict__ avd, int n)
{
    constexpr int K = 64, PAD = K + 1;
    __shared__ float Ws[K * H];
    __shared__ float xs[128 * PAD];
    __shared__ float as_s[H], ad_s[H];
    __shared__ float smax[8];
    const int tid  = threadIdx.x;
    const int base = blockIdx.x * 128;

    for (int i = tid; i < K * H; i += 256) Ws[i] = W[i];
    if (tid < H) { as_s[tid] = avs[tid]; ad_s[tid] = avd[tid]; }

    int rows = n - base; if (rows > 128) rows = 128;
    for (int i = tid; i < rows * K; i += 256) {
        int r = i / K, c = i - r * K;
        xs[r * PAD + c] = in[(size_t)(base + r) * K + c];
    }
    __syncthreads();

    const int r     = tid >> 1;
    const bool valid = (r < rows);
    const int rc    = valid ? r : 0;
    const int half  = tid & 1;

    float acc[32];
#pragma unroll
    for (int j = 0; j < 32; j++) acc[j] = 0.f;

    const float* xrow = &xs[rc * PAD];
#pragma unroll 4
    for (int k = 0; k < K; k++) {
        float xv = xrow[k];
        const float4* w4 = (const float4*)&Ws[k * H];
#pragma unroll
        for (int j = 0; j < 8; j++) {
            float4 w = w4[j * 2 + half];
            acc[4*j+0] = fmaf(xv, w.x, acc[4*j+0]);
            acc[4*j+1] = fmaf(xv, w.y, acc[4*j+1]);
            acc[4*j+2] = fmaf(xv, w.z, acc[4*j+2]);
            acc[4*j+3] = fmaf(xv, w.w, acc[4*j+3]);
        }
    }

    float as = 0.f, ad = 0.f;
#pragma unroll
    for (int j = 0; j < 8; j++) {
#pragma unroll
        for (int q = 0; q < 4; q++) {
            int ch = (j * 2 + half) * 4 + q;
            as = fmaf(acc[4*j+q], as_s[ch], as);
            ad = fmaf(acc[4*j+q], ad_s[ch], ad);
        }
    }
    as += __shfl_xor_sync(0xffffffffu, as, 1);
    ad += __shfl_xor_sync(0xffffffffu, ad, 1);

    const int node = base + r;
    if (valid) {
        if (half == 0) { g_as[node] = as; g_ad[node] = ad; }
        float4* o4 = (float4*)&out[(size_t)node * H];
#pragma unroll
        for (int j = 0; j < 8; j++)
            o4[j * 2 + half] = make_float4(acc[4*j], acc[4*j+1], acc[4*j+2], acc[4*j+3]);
    }

    // block max of as -> one atomicMax per block
    float amax = valid ? as : -3.4e38f;
#pragma unroll
    for (int o = 16; o; o >>= 1)
        amax = fmaxf(amax, __shfl_xor_sync(0xffffffffu, amax, o));
    if ((tid & 31) == 0) smax[tid >> 5] = amax;
    __syncthreads();
    if (tid == 0) {
        float m = smax[0];
#pragma unroll
        for (int w = 1; w < 8; w++) m = fmaxf(m, smax[w]);
        atomicMax(&g_asmax, enc_f(m));
    }
}

// ---------------- GAT gather: single pass, global-max shift ----------------
__global__ void __launch_bounds__(256) k_gat_gather(
    const float* __restrict__ h2, const float* __restrict__ b2,
    float* __restrict__ out, int n)
{
    int t = blockIdx.x * blockDim.x + threadIdx.x;
    int node = t >> 4;
    if (node >= n) return;
    int c = t & 15;

    int beg = g_row[node], end = g_row[node + 1];
    float ad_d  = g_ad[node];
    float M     = dec_f(g_asmax);
    float m     = leaky(M + ad_d);           // >= every e on this node (leaky monotone)
    float eself = leaky(g_as[node] + ad_d);

    float4 acc = make_float4(0.f, 0.f, 0.f, 0.f);
    float den = 0.f;
    int i = beg;
    for (; i + 2 <= end; i += 2) {
        int s0 = __ldg(&g_csrc[i]);
        int s1 = __ldg(&g_csrc[i + 1]);
        float p0 = __expf(leaky(__ldg(&g_as[s0]) + ad_d) - m);
        float p1 = __expf(leaky(__ldg(&g_as[s1]) + ad_d) - m);
        float4 v0 = __ldg((const float4*)h2 + (size_t)s0 * 16 + c);
        float4 v1 = __ldg((const float4*)h2 + (size_t)s1 * 16 + c);
        acc.x += p0 * v0.x + p1 * v1.x;
        acc.y += p0 * v0.y + p1 * v1.y;
        acc.z += p0 * v0.z + p1 * v1.z;
        acc.w += p0 * v0.w + p1 * v1.w;
        den += p0 + p1;
    }
    if (i < end) {
        int s0 = __ldg(&g_csrc[i]);
        float p0 = __expf(leaky(__ldg(&g_as[s0]) + ad_d) - m);
        float4 v0 = __ldg((const float4*)h2 + (size_t)s0 * 16 + c);
        acc.x += p0 * v0.x; acc.y += p0 * v0.y;
        acc.z += p0 * v0.z; acc.w += p0 * v0.w;
        den += p0;
    }

    float pself = __expf(eself - m);
    float w = 1.f / (den + pself);
    float4 hd = __ldg((const float4*)h2 + (size_t)node * 16 + c);
    float4 bb = __ldg((const float4*)b2 + c);
    float4 rr;
    rr.x = fmaxf(fmaf(acc.x + pself * hd.x, w, bb.x), 0.f);
    rr.y = fmaxf(fmaf(acc.y + pself * hd.y, w, bb.y), 0.f);
    rr.z = fmaxf(fmaf(acc.z + pself * hd.z, w, bb.z), 0.f);
    rr.w = fmaxf(fmaf(acc.w + pself * hd.w, w, bb.w), 0.f);
    ((float4*)&out[(size_t)node * H])[c] = rr;
}

// ---------------- GCN3 + heads fused with gather64: 64 nodes/block, 128 threads --------
__global__ void __launch_bounds__(128) k_gcn3_heads(
    const float* __restrict__ h, const float* __restrict__ W,
    const float* __restrict__ b3,
    const float* __restrict__ Wopt, const float* __restrict__ bopt,
    const float* __restrict__ Wb1,  const float* __restrict__ bb1,
    const float* __restrict__ Wb2,  const float* __restrict__ bb2,
    float* __restrict__ out_opt, float* __restrict__ out_bot, int n)
{
    constexpr int K = 64, PADN = 65;
    __shared__ float Ws[K * H];        // 16KB
    __shared__ float xsT[K * PADN];    // 16.6KB
    __shared__ float bs[H];
    __shared__ float sWopt[H * 10], sbopt[10], sWb1[H * 32], sbb1[32], sWb2[32], sbb2[1];
    __shared__ float sEmb[H];
    const int tid  = threadIdx.x;
    const int base = blockIdx.x * 64;

    for (int i = tid; i < K * H; i += 128) Ws[i] = W[i];
    for (int i = tid; i < H * 10; i += 128) sWopt[i] = Wopt[i];
    for (int i = tid; i < H * 32; i += 128) sWb1[i] = Wb1[i];
    if (tid < H)  { bs[tid] = b3[tid]; sEmb[tid] = 0.f; }
    if (tid < 32) { sbb1[tid] = bb1[tid]; sWb2[tid] = Wb2[tid]; }
    if (tid < 10) sbopt[tid] = bopt[tid];
    if (tid == 0) sbb2[0] = bb2[0];

    int rows = n - base; if (rows > 64) rows = 64;

    // gather stage: 8 passes of 8 nodes, 16 lanes/node
    const int c = tid & 15;
    for (int pass = 0; pass < 8; pass++) {
        int r = pass * 8 + (tid >> 4);
        int node = base + r;
        if (r < rows) {
            int beg = g_row[node], end = g_row[node + 1];
            float dd = g_dinv[node];
            float4 self = __ldg((const float4*)h + (size_t)node * 16 + c);
            float4 acc = make_float4(self.x * dd, self.y * dd, self.z * dd, self.w * dd);
            int i = beg;
            for (; i + 2 <= end; i += 2) {
                int s0 = __ldg(&g_csrc[i]);
                int s1 = __ldg(&g_csrc[i + 1]);
                float d0 = __ldg(&g_dinv[s0]);
                float d1 = __ldg(&g_dinv[s1]);
                float4 v0 = __ldg((const float4*)h + (size_t)s0 * 16 + c);
                float4 v1 = __ldg((const float4*)h + (size_t)s1 * 16 + c);
                acc.x += d0 * v0.x + d1 * v1.x;
                acc.y += d0 * v0.y + d1 * v1.y;
                acc.z += d0 * v0.z + d1 * v1.z;
                acc.w += d0 * v0.w + d1 * v1.w;
            }
            if (i < end) {
                int s0 = __ldg(&g_csrc[i]);
                float d0 = __ldg(&g_dinv[s0]);
                float4 v0 = __ldg((const float4*)h + (size_t)s0 * 16 + c);
                acc.x += d0 * v0.x; acc.y += d0 * v0.y;
                acc.z += d0 * v0.z; acc.w += d0 * v0.w;
            }
            int chb = c * 4;
            xsT[(chb + 0) * PADN + r] = acc.x;
            xsT[(chb + 1) * PADN + r] = acc.y;
            xsT[(chb + 2) * PADN + r] = acc.z;
            xsT[(chb + 3) * PADN + r] = acc.w;
        }
    }
    __syncthreads();

    // GEMM stage
    const int r     = tid >> 1;
    const bool valid = (r < rows);
    const int rc    = valid ? r : 0;
    const int half  = tid & 1;

    float acc[32];
#pragma unroll
    for (int j = 0; j < 32; j++) acc[j] = 0.f;

#pragma unroll 4
    for (int k = 0; k < K; k++) {
        float xv = xsT[k * PADN + rc];
        const float4* w4 = (const float4*)&Ws[k * H];
#pragma unroll
        for (int j = 0; j < 8; j++) {
            float4 w = w4[j * 2 + half];
            acc[4*j+0] = fmaf(xv, w.x, acc[4*j+0]);
            acc[4*j+1] = fmaf(xv, w.y, acc[4*j+1]);
            acc[4*j+2] = fmaf(xv, w.z, acc[4*j+2]);
            acc[4*j+3] = fmaf(xv, w.w, acc[4*j+3]);
        }
    }

    const int node = base + r;
    float d = valid ? g_dinv[node] : 0.f;

    // h3 = relu(d*acc + b3); zero for invalid threads
#pragma unroll
    for (int j = 0; j < 8; j++) {
#pragma unroll
        for (int q = 0; q < 4; q++) {
            int ch = (j * 2 + half) * 4 + q;
            float v = fmaxf(fmaf(acc[4*j+q], d, bs[ch]), 0.f);
            acc[4*j+q] = valid ? v : 0.f;
        }
    }

    // opt logits
#pragma unroll
    for (int cc = 0; cc < 10; cc++) {
        float p = 0.f;
#pragma unroll
        for (int j = 0; j < 8; j++) {
#pragma unroll
            for (int q = 0; q < 4; q++) {
                int ch = (j * 2 + half) * 4 + q;
                p = fmaf(acc[4*j+q], sWopt[ch * 10 + cc], p);
            }
        }
        p += __shfl_xor_sync(0xffffffffu, p, 1);
        if (valid && half == 0) out_opt[(size_t)node * 10 + cc] = p + sbopt[cc];
    }

    // bottleneck MLP
    float z = 0.f;
#pragma unroll
    for (int mm = 0; mm < 32; mm++) {
        float s = 0.f;
#pragma unroll
        for (int j = 0; j < 8; j++) {
#pragma unroll
            for (int q = 0; q < 4; q++) {
                int ch = (j * 2 + half) * 4 + q;
                s = fmaf(acc[4*j+q], sWb1[ch * 32 + mm], s);
            }
        }
        s += __shfl_xor_sync(0xffffffffu, s, 1);
        z = fmaf(fmaxf(s + sbb1[mm], 0.f), sWb2[mm], z);
    }
    if (valid && half == 0) out_bot[node] = 1.f / (1.f + expf(-(z + sbb2[0])));

    // embedding: parity-preserving warp reduce -> smem -> one global atomic per channel
    const int lane = tid & 31;
#pragma unroll
    for (int idx = 0; idx < 32; idx++) {
        float v = acc[idx];
        v += __shfl_xor_sync(0xffffffffu, v, 2);
        v += __shfl_xor_sync(0xffffffffu, v, 4);
        v += __shfl_xor_sync(0xffffffffu, v, 8);
        v += __shfl_xor_sync(0xffffffffu, v, 16);
        if (lane < 2) {
            int ch = ((idx >> 2) * 2 + half) * 4 + (idx & 3);
            atomicAdd(&sEmb[ch], v);
        }
    }
    __syncthreads();
    if (tid < H) atomicAdd(&g_embed[tid], sEmb[tid]);
}

__global__ void k_embed_final(float* __restrict__ emb_out, float inv_n) {
    int t = threadIdx.x;
    if (t < H) emb_out[t] = g_embed[t] * inv_n;
}

// ---------------- launcher ----------------
extern "C" void kernel_launch(void* const* d_in, const int* in_sizes, int n_in,
                              void* d_out, int out_size)
{
    const float* x    = (const float*)d_in[0];
    const int*   ei   = (const int*)  d_in[1];
    const float* W1   = (const float*)d_in[2];
    const float* b1   = (const float*)d_in[3];
    const float* W2   = (const float*)d_in[4];
    const float* avs  = (const float*)d_in[5];
    const float* avd  = (const float*)d_in[6];
    const float* b2   = (const float*)d_in[7];
    const float* W3   = (const float*)d_in[8];
    const float* b3   = (const float*)d_in[9];
    const float* Wopt = (const float*)d_in[10];
    const float* bopt = (const float*)d_in[11];
    const float* Wb1  = (const float*)d_in[12];
    const float* bb1  = (const float*)d_in[13];
    const float* Wb2  = (const float*)d_in[14];
    const float* bb2  = (const float*)d_in[15];

    const int n = in_sizes[0] / 32;   // F = 32
    const int e = in_sizes[1] / 2;
    const int* src = ei;
    const int* dst = ei + e;

    float* out_opt = (float*)d_out;
    float* out_bot = out_opt + (size_t)n * 10;
    float* out_emb = out_bot + n;

    float *bufA = nullptr, *bufB = nullptr;
    cudaGetSymbolAddress((void**)&bufA, g_bufA);
    cudaGetSymbolAddress((void**)&bufB, g_bufB);

    const int B = 256;
    const int gN   = (n + B - 1) / B;
    const int gE   = (e + B - 1) / B;
    const int gN16 = (n * 16 + B - 1) / B;
    const int nb   = (n + 1023) / 1024;

    // CSR build
    k_prep<<<gN, B>>>(n);
    k_deg<<<gE, B>>>(dst, e);
    k_scan1<<<nb, 1024>>>(n);
    k_scan2<<<1, 128>>>(nb);
    k_scan3<<<gN, B>>>(n, e);
    k_csr<<<gE, B>>>(src, dst, e);

    // GCN layer 1 (fused gather+GEMM)
    k_gcn1<<<(n + 127) / 128, 256>>>(x, W1, b1, bufB, n);

    // GAT layer
    k_gat_gemm<<<(n + 127) / 128, 256>>>(bufB, W2, bufA, avs, avd, n);
    k_gat_gather<<<gN16, B>>>(bufA, b2, bufB, n);

    // GCN layer 3 + heads (fused gather+GEMM+heads)
    k_gcn3_heads<<<(n + 63) / 64, 128>>>(bufB, W3, b3, Wopt, bopt, Wb1, bb1, Wb2, bb2,
                                         out_opt, out_bot, n);

    k_embed_final<<<1, 64>>>(out_emb, 1.0f / (float)n);
}

// round 8
// speedup vs baseline: 1.0437x; 1.0437x over previous
#include <cuda_runtime.h>
#include <math.h>

#define NN 100000
#define EE 1250000
#define H  64

// ---------------- scratch (static __device__ — no allocation allowed) ----------------
__device__ __align__(16) float g_bufA[NN * H];
__device__ __align__(16) float g_bufB[NN * H];
__device__ __align__(16) float g_t32 [NN * 32];
__device__ float g_dinv [NN];
__device__ float g_as   [NN];
__device__ float g_ad   [NN];
__device__ int   g_degi [NN];
__device__ int   g_scan [NN];
__device__ int   g_bsum [128];
__device__ int   g_boff [128];
__device__ int   g_row  [NN + 1];
__device__ int   g_cur  [NN];
__device__ int   g_csrc [EE];
__device__ int   g_asmax;
__device__ __align__(16) float g_embed[H];

__device__ __forceinline__ float leaky(float v) { return v > 0.f ? v : 0.2f * v; }
__device__ __forceinline__ int enc_f(float f) {
    int i = __float_as_int(f);
    return i >= 0 ? i : (i ^ 0x7FFFFFFF);
}
__device__ __forceinline__ float dec_f(int i) {
    return __int_as_float(i >= 0 ? i : (i ^ 0x7FFFFFFF));
}

// ---------------- prep: zero degree histogram + embed + asmax ----------------
__global__ void k_prep(int n) {
    int t = blockIdx.x * blockDim.x + threadIdx.x;
    if (t < n) g_degi[t] = 0;
    if (t < 16) ((float4*)g_embed)[t] = make_float4(0.f, 0.f, 0.f, 0.f);
    if (t == 0) g_asmax = (int)0x80000000;   // INT_MIN
}

__global__ void k_deg(const int* __restrict__ dst, int e) {
    int t = blockIdx.x * blockDim.x + threadIdx.x;
    if (t < e) atomicAdd(&g_degi[dst[t]], 1);
}

// ---------------- scans (warp-shuffle based) ----------------
__global__ void k_scan1(int n) {
    __shared__ int wsum[32];
    int i = blockIdx.x * 1024 + threadIdx.x;
    int lane = threadIdx.x & 31, wid = threadIdx.x >> 5;
    int v = (i < n) ? g_degi[i] : 0;
    int s = v;
#pragma unroll
    for (int o = 1; o < 32; o <<= 1) {
        int u = __shfl_up_sync(0xffffffffu, s, o);
        if (lane >= o) s += u;
    }
    if (lane == 31) wsum[wid] = s;
    __syncthreads();
    if (wid == 0) {
        int w = wsum[lane];
#pragma unroll
        for (int o = 1; o < 32; o <<= 1) {
            int u = __shfl_up_sync(0xffffffffu, w, o);
            if (lane >= o) w += u;
        }
        wsum[lane] = w;
    }
    __syncthreads();
    int off = wid ? wsum[wid - 1] : 0;
    s += off;
    if (i < n) g_scan[i] = s;                        // inclusive
    if (threadIdx.x == 1023) g_bsum[blockIdx.x] = s; // block total
}

__global__ void k_scan2(int nb) {
    __shared__ int wsum[4];
    int t = threadIdx.x, lane = t & 31, wid = t >> 5;
    int v = (t < nb) ? g_bsum[t] : 0;
    int s = v;
#pragma unroll
    for (int o = 1; o < 32; o <<= 1) {
        int u = __shfl_up_sync(0xffffffffu, s, o);
        if (lane >= o) s += u;
    }
    if (lane == 31) wsum[wid] = s;
    __syncthreads();
    int off = 0;
    if (wid > 0) off += wsum[0];
    if (wid > 1) off += wsum[1];
    if (wid > 2) off += wsum[2];
    if (t < nb) g_boff[t] = s + off - v;  // exclusive across blocks
}

__global__ void k_scan3(int n, int e) {
    int i = blockIdx.x * blockDim.x + threadIdx.x;
    if (i < n) {
        int d = g_degi[i];
        int start = g_scan[i] - d + g_boff[i >> 10];
        g_row[i] = start;
        g_cur[i] = start;
        g_dinv[i] = rsqrtf((float)(d + 1));   // +1 self-loop
    }
    if (i == 0) g_row[n] = e;
}

__global__ void k_csr(const int* __restrict__ src, const int* __restrict__ dst, int e) {
    int t = blockIdx.x * blockDim.x + threadIdx.x;
    if (t >= e) return;
    int pos = atomicAdd(&g_cur[dst[t]], 1);
    g_csrc[pos] = src[t];
}

// ---------------- gather in F=32 space: t = dinv_d*x[d] + Σ dinv_s*x[s]  (8 lanes/node) ----
__global__ void __launch_bounds__(256) k_gather32(const float* __restrict__ x,
                                                  float* __restrict__ t, int n)
{
    int tt = blockIdx.x * blockDim.x + threadIdx.x;
    int node = tt >> 3;
    if (node >= n) return;
    int c = tt & 7;

    int beg = g_row[node], end = g_row[node + 1];
    float dd = g_dinv[node];
    float4 self = __ldg((const float4*)x + (size_t)node * 8 + c);
    float4 acc = make_float4(self.x * dd, self.y * dd, self.z * dd, self.w * dd);

    int i = beg;
    for (; i + 2 <= end; i += 2) {
        int s0 = __ldg(&g_csrc[i]);
        int s1 = __ldg(&g_csrc[i + 1]);
        float d0 = __ldg(&g_dinv[s0]);
        float d1 = __ldg(&g_dinv[s1]);
        float4 v0 = __ldg((const float4*)x + (size_t)s0 * 8 + c);
        float4 v1 = __ldg((const float4*)x + (size_t)s1 * 8 + c);
        acc.x += d0 * v0.x + d1 * v1.x;
        acc.y += d0 * v0.y + d1 * v1.y;
        acc.z += d0 * v0.z + d1 * v1.z;
        acc.w += d0 * v0.w + d1 * v1.w;
    }
    if (i < end) {
        int s0 = __ldg(&g_csrc[i]);
        float d0 = __ldg(&g_dinv[s0]);
        float4 v0 = __ldg((const float4*)x + (size_t)s0 * 8 + c);
        acc.x += d0 * v0.x; acc.y += d0 * v0.y;
        acc.z += d0 * v0.z; acc.w += d0 * v0.w;
    }
    ((float4*)t)[(size_t)node * 8 + c] = acc;
}

// ---------------- gather in H=64 space: u = dinv_d*h[d] + Σ dinv_s*h[s]  (16 lanes/node) ----
__global__ void __launch_bounds__(256) k_gather64(const float* __restrict__ h,
                                                  float* __restrict__ u, int n)
{
    int tt = blockIdx.x * blockDim.x + threadIdx.x;
    int node = tt >> 4;
    if (node >= n) return;
    int c = tt & 15;

    int beg = g_row[node], end = g_row[node + 1];
    float dd = g_dinv[node];
    float4 self = __ldg((const float4*)h + (size_t)node * 16 + c);
    float4 acc = make_float4(self.x * dd, self.y * dd, self.z * dd, self.w * dd);

    int i = beg;
    for (; i + 2 <= end; i += 2) {
        int s0 = __ldg(&g_csrc[i]);
        int s1 = __ldg(&g_csrc[i + 1]);
        float d0 = __ldg(&g_dinv[s0]);
        float d1 = __ldg(&g_dinv[s1]);
        float4 v0 = __ldg((const float4*)h + (size_t)s0 * 16 + c);
        float4 v1 = __ldg((const float4*)h + (size_t)s1 * 16 + c);
        acc.x += d0 * v0.x + d1 * v1.x;
        acc.y += d0 * v0.y + d1 * v1.y;
        acc.z += d0 * v0.z + d1 * v1.z;
        acc.w += d0 * v0.w + d1 * v1.w;
    }
    if (i < end) {
        int s0 = __ldg(&g_csrc[i]);
        float d0 = __ldg(&g_dinv[s0]);
        float4 v0 = __ldg((const float4*)h + (size_t)s0 * 16 + c);
        acc.x += d0 * v0.x; acc.y += d0 * v0.y;
        acc.z += d0 * v0.z; acc.w += d0 * v0.w;
    }
    ((float4*)u)[(size_t)node * 16 + c] = acc;
}

// ---------------- GEMM: [n,K] @ [K,64] ; 128 nodes/block, 256 threads ----------------
// MODE 0: out = relu(dinv[node]*(in @ W) + bias)   (GCN, aggregate-first)
// MODE 1: out = in @ W ; alpha dots ; global as-max (GAT)
template <int K, int MODE>
__global__ void __launch_bounds__(256) k_gemm(
    const float* __restrict__ in, const float* __restrict__ W,
    float* __restrict__ out, const float* __restrict__ bias,
    const float* __restrict__ avs, const float* __restrict__ avd, int n)
{
    constexpr int PAD = K + 1;                 // odd -> conflict-free
    __shared__ float Ws[K * H];
    __shared__ float xs[128 * PAD];
    __shared__ float as_s[H], ad_s[H], bs[H];
    __shared__ float smax[8];
    const int tid  = threadIdx.x;
    const int base = blockIdx.x * 128;

    for (int i = tid; i < K * H; i += 256) Ws[i] = W[i];
    if (MODE == 1 && tid < H) { as_s[tid] = avs[tid]; ad_s[tid] = avd[tid]; }
    if (MODE == 0 && tid < H) bs[tid] = bias[tid];

    int rows = n - base; if (rows > 128) rows = 128;
    for (int i = tid; i < rows * K; i += 256) {
        int r = i / K, c = i - r * K;
        xs[r * PAD + c] = in[(size_t)(base + r) * K + c];
    }
    __syncthreads();

    const int r     = tid >> 1;
    const bool valid = (r < rows);
    const int rc    = valid ? r : 0;
    const int half  = tid & 1;

    float acc[32];
#pragma unroll
    for (int j = 0; j < 32; j++) acc[j] = 0.f;

    const float* xrow = &xs[rc * PAD];
#pragma unroll 4
    for (int k = 0; k < K; k++) {
        float xv = xrow[k];
        const float4* w4 = (const float4*)&Ws[k * H];
#pragma unroll
        for (int j = 0; j < 8; j++) {
            float4 w = w4[j * 2 + half];
            acc[4*j+0] = fmaf(xv, w.x, acc[4*j+0]);
            acc[4*j+1] = fmaf(xv, w.y, acc[4*j+1]);
            acc[4*j+2] = fmaf(xv, w.z, acc[4*j+2]);
            acc[4*j+3] = fmaf(xv, w.w, acc[4*j+3]);
        }
    }

    const int node = base + r;
    if (MODE == 0) {
        if (!valid) return;
        float d = g_dinv[node];
        float4* o4 = (float4*)&out[(size_t)node * H];
#pragma unroll
        for (int j = 0; j < 8; j++) {
            int ch = (j * 2 + half) * 4;
            o4[j * 2 + half] = make_float4(
                fmaxf(fmaf(acc[4*j+0], d, bs[ch+0]), 0.f),
                fmaxf(fmaf(acc[4*j+1], d, bs[ch+1]), 0.f),
                fmaxf(fmaf(acc[4*j+2], d, bs[ch+2]), 0.f),
                fmaxf(fmaf(acc[4*j+3], d, bs[ch+3]), 0.f));
        }
    } else {
        float as = 0.f, ad = 0.f;
#pragma unroll
        for (int j = 0; j < 8; j++) {
#pragma unroll
            for (int q = 0; q < 4; q++) {
                int ch = (j * 2 + half) * 4 + q;
                as = fmaf(acc[4*j+q], as_s[ch], as);
                ad = fmaf(acc[4*j+q], ad_s[ch], ad);
            }
        }
        as += __shfl_xor_sync(0xffffffffu, as, 1);
        ad += __shfl_xor_sync(0xffffffffu, ad, 1);
        if (valid) {
            if (half == 0) { g_as[node] = as; g_ad[node] = ad; }
            float4* o4 = (float4*)&out[(size_t)node * H];
#pragma unroll
            for (int j = 0; j < 8; j++)
                o4[j * 2 + half] = make_float4(acc[4*j], acc[4*j+1], acc[4*j+2], acc[4*j+3]);
        }
        // block max of as -> one atomicMax per block
        float amax = valid ? as : -3.4e38f;
#pragma unroll
        for (int o = 16; o; o >>= 1)
            amax = fmaxf(amax, __shfl_xor_sync(0xffffffffu, amax, o));
        if ((tid & 31) == 0) smax[tid >> 5] = amax;
        __syncthreads();
        if (tid == 0) {
            float m = smax[0];
#pragma unroll
            for (int w = 1; w < 8; w++) m = fmaxf(m, smax[w]);
            atomicMax(&g_asmax, enc_f(m));
        }
    }
}

// ---------------- GAT gather: single pass, global-max shift ----------------
__global__ void __launch_bounds__(256) k_gat_gather(
    const float* __restrict__ h2, const float* __restrict__ b2,
    float* __restrict__ out, int n)
{
    int t = blockIdx.x * blockDim.x + threadIdx.x;
    int node = t >> 4;
    if (node >= n) return;
    int c = t & 15;

    int beg = g_row[node], end = g_row[node + 1];
    float ad_d  = g_ad[node];
    float M     = dec_f(g_asmax);
    float m     = leaky(M + ad_d);           // >= every e on this node (leaky monotone)
    float eself = leaky(g_as[node] + ad_d);

    float4 acc = make_float4(0.f, 0.f, 0.f, 0.f);
    float den = 0.f;
    int i = beg;
    for (; i + 2 <= end; i += 2) {
        int s0 = __ldg(&g_csrc[i]);
        int s1 = __ldg(&g_csrc[i + 1]);
        float p0 = __expf(leaky(__ldg(&g_as[s0]) + ad_d) - m);
        float p1 = __expf(leaky(__ldg(&g_as[s1]) + ad_d) - m);
        float4 v0 = __ldg((const float4*)h2 + (size_t)s0 * 16 + c);
        float4 v1 = __ldg((const float4*)h2 + (size_t)s1 * 16 + c);
        acc.x += p0 * v0.x + p1 * v1.x;
        acc.y += p0 * v0.y + p1 * v1.y;
        acc.z += p0 * v0.z + p1 * v1.z;
        acc.w += p0 * v0.w + p1 * v1.w;
        den += p0 + p1;
    }
    if (i < end) {
        int s0 = __ldg(&g_csrc[i]);
        float p0 = __expf(leaky(__ldg(&g_as[s0]) + ad_d) - m);
        float4 v0 = __ldg((const float4*)h2 + (size_t)s0 * 16 + c);
        acc.x += p0 * v0.x; acc.y += p0 * v0.y;
        acc.z += p0 * v0.z; acc.w += p0 * v0.w;
        den += p0;
    }

    float pself = __expf(eself - m);
    float w = 1.f / (den + pself);
    float4 hd = __ldg((const float4*)h2 + (size_t)node * 16 + c);
    float4 bb = __ldg((const float4*)b2 + c);
    float4 rr;
    rr.x = fmaxf(fmaf(acc.x + pself * hd.x, w, bb.x), 0.f);
    rr.y = fmaxf(fmaf(acc.y + pself * hd.y, w, bb.y), 0.f);
    rr.z = fmaxf(fmaf(acc.z + pself * hd.z, w, bb.z), 0.f);
    rr.w = fmaxf(fmaf(acc.w + pself * hd.w, w, bb.w), 0.f);
    ((float4*)&out[(size_t)node * H])[c] = rr;
}

// ---------------- GEMM3 + heads fused: h3 = relu(dinv*(u@W3)+b3); opt/bottleneck/embed ----
__global__ void __launch_bounds__(256) k_gemm3_heads(
    const float* __restrict__ in, const float* __restrict__ W,
    const float* __restrict__ b3,
    const float* __restrict__ Wopt, const float* __restrict__ bopt,
    const float* __restrict__ Wb1,  const float* __restrict__ bb1,
    const float* __restrict__ Wb2,  const float* __restrict__ bb2,
    float* __restrict__ out_opt, float* __restrict__ out_bot, int n)
{
    constexpr int K = 64, PAD = K + 1;
    __shared__ float Ws[K * H];
    __shared__ float xs[128 * PAD];
    __shared__ float bs[H];
    __shared__ float sWopt[H * 10], sbopt[10], sWb1[H * 32], sbb1[32], sWb2[32], sbb2[1];
    __shared__ float sEmb[H];
    const int tid  = threadIdx.x;
    const int base = blockIdx.x * 128;

    for (int i = tid; i < K * H; i += 256) Ws[i] = W[i];
    for (int i = tid; i < H * 10; i += 256) sWopt[i] = Wopt[i];
    for (int i = tid; i < H * 32; i += 256) sWb1[i] = Wb1[i];
    if (tid < H)  { bs[tid] = b3[tid]; sEmb[tid] = 0.f; }
    if (tid < 32) { sbb1[tid] = bb1[tid]; sWb2[tid] = Wb2[tid]; }
    if (tid < 10) sbopt[tid] = bopt[tid];
    if (tid == 0) sbb2[0] = bb2[0];

    int rows = n - base; if (rows > 128) rows = 128;
    for (int i = tid; i < rows * K; i += 256) {
        int r = i / K, c = i - r * K;
        xs[r * PAD + c] = in[(size_t)(base + r) * K + c];
    }
    __syncthreads();

    const int r     = tid >> 1;
    const bool valid = (r < rows);
    const int rc    = valid ? r : 0;
    const int half  = tid & 1;

    float acc[32];
#pragma unroll
    for (int j = 0; j < 32; j++) acc[j] = 0.f;

    const float* xrow = &xs[rc * PAD];
#pragma unroll 4
    for (int k = 0; k < K; k++) {
        float xv = xrow[k];
        const float4* w4 = (const float4*)&Ws[k * H];
#pragma unroll
        for (int j = 0; j < 8; j++) {
            float4 w = w4[j * 2 + half];
            acc[4*j+0] = fmaf(xv, w.x, acc[4*j+0]);
            acc[4*j+1] = fmaf(xv, w.y, acc[4*j+1]);
            acc[4*j+2] = fmaf(xv, w.z, acc[4*j+2]);
            acc[4*j+3] = fmaf(xv, w.w, acc[4*j+3]);
        }
    }

    const int node = base + r;
    float d = valid ? g_dinv[node] : 0.f;

    // h3 in place of acc: relu(d*acc + b3[ch]); force 0 for invalid threads
#pragma unroll
    for (int j = 0; j < 8; j++) {
#pragma unroll
        for (int q = 0; q < 4; q++) {
            int ch = (j * 2 + half) * 4 + q;
            float v = fmaxf(fmaf(acc[4*j+q], d, bs[ch]), 0.f);
            acc[4*j+q] = valid ? v : 0.f;
        }
    }

    // opt logits: 10 dots, combine halves via shfl
#pragma unroll
    for (int c = 0; c < 10; c++) {
        float p = 0.f;
#pragma unroll
        for (int j = 0; j < 8; j++) {
#pragma unroll
            for (int q = 0; q < 4; q++) {
                int ch = (j * 2 + half) * 4 + q;
                p = fmaf(acc[4*j+q], sWopt[ch * 10 + c], p);
            }
        }
        p += __shfl_xor_sync(0xffffffffu, p, 1);
        if (valid && half == 0) out_opt[(size_t)node * 10 + c] = p + sbopt[c];
    }

    // bottleneck MLP
    float z = 0.f;
#pragma unroll
    for (int m = 0; m < 32; m++) {
        float s = 0.f;
#pragma unroll
        for (int j = 0; j < 8; j++) {
#pragma unroll
            for (int q = 0; q < 4; q++) {
                int ch = (j * 2 + half) * 4 + q;
                s = fmaf(acc[4*j+q], sWb1[ch * 32 + m], s);
            }
        }
        s += __shfl_xor_sync(0xffffffffu, s, 1);
        z = fmaf(fmaxf(s + sbb1[m], 0.f), sWb2[m], z);
    }
    if (valid && half == 0) out_bot[node] = 1.f / (1.f + expf(-(z + sbb2[0])));

    // embedding: parity-preserving warp reduce (lanes of same half), then smem, then global
    const int lane = tid & 31;
#pragma unroll
    for (int idx = 0; idx < 32; idx++) {
        float v = acc[idx];
        v += __shfl_xor_sync(0xffffffffu, v, 2);
        v += __shfl_xor_sync(0xffffffffu, v, 4);
        v += __shfl_xor_sync(0xffffffffu, v, 8);
        v += __shfl_xor_sync(0xffffffffu, v, 16);
        if (lane < 2) {
            int ch = ((idx >> 2) * 2 + half) * 4 + (idx & 3);
            atomicAdd(&sEmb[ch], v);
        }
    }
    __syncthreads();
    if (tid < H) atomicAdd(&g_embed[tid], sEmb[tid]);
}

__global__ void k_embed_final(float* __restrict__ emb_out, float inv_n) {
    int t = threadIdx.x;
    if (t < H) emb_out[t] = g_embed[t] * inv_n;
}

// ---------------- launcher ----------------
extern "C" void kernel_launch(void* const* d_in, const int* in_sizes, int n_in,
                              void* d_out, int out_size)
{
    const float* x    = (const float*)d_in[0];
    const int*   ei   = (const int*)  d_in[1];
    const float* W1   = (const float*)d_in[2];
    const float* b1   = (const float*)d_in[3];
    const float* W2   = (const float*)d_in[4];
    const float* avs  = (const float*)d_in[5];
    const float* avd  = (const float*)d_in[6];
    const float* b2   = (const float*)d_in[7];
    const float* W3   = (const float*)d_in[8];
    const float* b3   = (const float*)d_in[9];
    const float* Wopt = (const float*)d_in[10];
    const float* bopt = (const float*)d_in[11];
    const float* Wb1  = (const float*)d_in[12];
    const float* bb1  = (const float*)d_in[13];
    const float* Wb2  = (const float*)d_in[14];
    const float* bb2  = (const float*)d_in[15];

    const int n = in_sizes[0] / 32;   // F = 32
    const int e = in_sizes[1] / 2;
    const int* src = ei;
    const int* dst = ei + e;

    float* out_opt = (float*)d_out;
    float* out_bot = out_opt + (size_t)n * 10;
    float* out_emb = out_bot + n;

    float *bufA = nullptr, *bufB = nullptr, *t32 = nullptr;
    cudaGetSymbolAddress((void**)&bufA, g_bufA);
    cudaGetSymbolAddress((void**)&bufB, g_bufB);
    cudaGetSymbolAddress((void**)&t32,  g_t32);

    const int B = 256;
    const int gN   = (n + B - 1) / B;
    const int gE   = (e + B - 1) / B;
    const int gN8  = (n * 8  + B - 1) / B;
    const int gN16 = (n * 16 + B - 1) / B;
    const int gG   = (n + 127) / 128;
    const int nb   = (n + 1023) / 1024;

    // CSR build (degree histogram -> scan -> cursor scatter)
    k_prep<<<gN, B>>>(n);
    k_deg<<<gE, B>>>(dst, e);
    k_scan1<<<nb, 1024>>>(n);
    k_scan2<<<1, 128>>>(nb);
    k_scan3<<<gN, B>>>(n, e);
    k_csr<<<gE, B>>>(src, dst, e);

    // GCN layer 1: aggregate in F=32 space, then transform
    k_gather32<<<gN8, B>>>(x, t32, n);
    k_gemm<32, 0><<<gG, 256>>>(t32, W1, bufB, b1, nullptr, nullptr, n);

    // GAT layer (single-pass softmax via global as-max)
    k_gemm<64, 1><<<gG, 256>>>(bufB, W2, bufA, nullptr, avs, avd, n);
    k_gat_gather<<<gN16, B>>>(bufA, b2, bufB, n);

    // GCN layer 3: aggregate-first, then fused transform + heads
    k_gather64<<<gN16, B>>>(bufB, bufA, n);
    k_gemm3_heads<<<gG, 256>>>(bufA, W3, b3, Wopt, bopt, Wb1, bb1, Wb2, bb2,
                               out_opt, out_bot, n);

    k_embed_final<<<1, 64>>>(out_emb, 1.0f / (float)n);
}